// round 1
// baseline (speedup 1.0000x reference)
#include <cuda_runtime.h>
#include <cuda_bf16.h>
#include <cstdint>

// Problem constants (fixed by the reference)
#define NC   1024      // n_concepts (K)
#define NL   512       // n_lemmas   (N)
#define BTOT 4096      // batch      (M)
#define TSTEPS 50
#define GAMMA_C 0.95f
#define KAPPA_C 0.1f
#define FLOOR_C 1e-6f

// Scratch: drive = c_lex @ W^T  (loop-invariant term of the recurrence)
__device__ float g_drive[(size_t)BTOT * NL];

// ---------------------------------------------------------------------------
// SGEMM: D[M,NL] = A[M,NC] * W[NL,NC]^T   (both operands K-contiguous)
// Tile 128x64, K-step 16, 256 threads, 8x4 micro-tile per thread.
// ---------------------------------------------------------------------------
#define BM 128
#define BN 64
#define BK 16

__global__ __launch_bounds__(256) void sgemm_drive_kernel(
    const float* __restrict__ A, const float* __restrict__ Wm,
    float* __restrict__ D)
{
    __shared__ float As[BK][BM + 4];   // +4 pad: conflict-free, keeps 16B align
    __shared__ float Bs[BK][BN + 4];

    const int tid = threadIdx.x;
    const int tx  = tid & 15;          // 0..15 -> N
    const int ty  = tid >> 4;          // 0..15 -> M
    const int m0  = blockIdx.y * BM;
    const int n0  = blockIdx.x * BN;

    float acc[8][4];
    #pragma unroll
    for (int i = 0; i < 8; i++)
        #pragma unroll
        for (int j = 0; j < 4; j++) acc[i][j] = 0.f;

    for (int k0 = 0; k0 < NC; k0 += BK) {
        // ---- load A tile: 128 rows x 16 k  (512 float4, 2 per thread) ----
        #pragma unroll
        for (int it = 0; it < 2; it++) {
            int g  = tid + it * 256;
            int m  = g >> 2;
            int kk = (g & 3) << 2;
            float4 v = *reinterpret_cast<const float4*>(
                &A[(size_t)(m0 + m) * NC + k0 + kk]);
            As[kk + 0][m] = v.x; As[kk + 1][m] = v.y;
            As[kk + 2][m] = v.z; As[kk + 3][m] = v.w;
        }
        // ---- load W tile: Bs[k][n] = W[n0+n][k0+k]  (256 float4, 1/thr) ----
        {
            int n  = tid >> 2;
            int kk = (tid & 3) << 2;
            float4 v = *reinterpret_cast<const float4*>(
                &Wm[(size_t)(n0 + n) * NC + k0 + kk]);
            Bs[kk + 0][n] = v.x; Bs[kk + 1][n] = v.y;
            Bs[kk + 2][n] = v.z; Bs[kk + 3][n] = v.w;
        }
        __syncthreads();

        #pragma unroll
        for (int k = 0; k < BK; k++) {
            float af[8], bf[4];
            #pragma unroll
            for (int i = 0; i < 8; i++) af[i] = As[k][ty * 8 + i];
            #pragma unroll
            for (int j = 0; j < 4; j++) bf[j] = Bs[k][tx * 4 + j];
            #pragma unroll
            for (int i = 0; i < 8; i++)
                #pragma unroll
                for (int j = 0; j < 4; j++)
                    acc[i][j] = fmaf(af[i], bf[j], acc[i][j]);
        }
        __syncthreads();
    }

    // ---- store (float4 along N) ----
    #pragma unroll
    for (int i = 0; i < 8; i++) {
        float4 v = make_float4(acc[i][0], acc[i][1], acc[i][2], acc[i][3]);
        *reinterpret_cast<float4*>(
            &D[(size_t)(m0 + ty * 8 + i) * NL + n0 + tx * 4]) = v;
    }
}

// ---------------------------------------------------------------------------
// Recurrence + selection: one warp per batch row. a,d in registers (16/lane).
// a <- gamma*a + d ;  s = sum(a) ;  a <- relu((1+k)*a - k*s)   x TSTEPS
// Then peak/argmax/mean -> outputs.
// Output layout: [ a : B*NL floats | selected : B floats | confidence : B ]
// ---------------------------------------------------------------------------
__global__ __launch_bounds__(256) void iterate_kernel(
    const float* __restrict__ D, const float* __restrict__ a0,
    float* __restrict__ out, int B, int write_aux)
{
    const int warp = (blockIdx.x * blockDim.x + threadIdx.x) >> 5;
    const int lane = threadIdx.x & 31;
    if (warp >= B) return;

    const size_t rowoff = (size_t)warp * NL;
    float dv[16], a[16];
    #pragma unroll
    for (int i = 0; i < 16; i++) {
        dv[i] = D [rowoff + lane + 32 * i];
        a[i]  = a0[rowoff + lane + 32 * i];
    }

    const float c1 = 1.0f + KAPPA_C;
    #pragma unroll 1
    for (int t = 0; t < TSTEPS; t++) {
        float p = 0.f;
        #pragma unroll
        for (int i = 0; i < 16; i++) {
            a[i] = fmaf(GAMMA_C, a[i], dv[i]);
            p += a[i];
        }
        #pragma unroll
        for (int o = 16; o; o >>= 1) p += __shfl_xor_sync(0xffffffffu, p, o);
        const float nks = -KAPPA_C * p;
        #pragma unroll
        for (int i = 0; i < 16; i++)
            a[i] = fmaxf(fmaf(c1, a[i], nks), 0.f);
    }

    // per-lane max (first index wins via strict >) + sum
    float s = 0.f, m = -1.f;
    int mi = NL;
    #pragma unroll
    for (int i = 0; i < 16; i++) {
        float v = a[i];
        s += v;
        if (v > m) { m = v; mi = lane + 32 * i; }
    }
    // cross-lane reduce; tie -> smaller index (matches argmax first-index)
    #pragma unroll
    for (int o = 16; o; o >>= 1) {
        float om  = __shfl_xor_sync(0xffffffffu, m,  o);
        int   omi = __shfl_xor_sync(0xffffffffu, mi, o);
        float os  = __shfl_xor_sync(0xffffffffu, s,  o);
        s += os;
        if (om > m || (om == m && omi < mi)) { m = om; mi = omi; }
    }

    // write a row (coalesced)
    #pragma unroll
    for (int i = 0; i < 16; i++)
        out[rowoff + lane + 32 * i] = a[i];

    if (lane == 0 && write_aux) {
        const size_t base = (size_t)B * NL;
        out[base + warp]     = (float)mi;
        out[base + B + warp] = m / fmaxf(s * (1.0f / NL), FLOOR_C);
    }
}

extern "C" void kernel_launch(void* const* d_in, const int* in_sizes, int n_in,
                              void* d_out, int out_size)
{
    const float* c_lex = (const float*)d_in[0];   // (B, 1024)
    const float* W     = (const float*)d_in[1];   // (512, 1024)
    const float* a0    = (const float*)d_in[2];   // (B, 512)
    float* out = (float*)d_out;

    const int B = in_sizes[0] / NC;               // 4096

    float* drive = nullptr;
    cudaGetSymbolAddress((void**)&drive, g_drive);

    // Phase 1: drive = c_lex @ W^T
    dim3 gblock(256);
    dim3 ggrid(NL / BN, B / BM);                  // (8, 32) = 256 CTAs
    sgemm_drive_kernel<<<ggrid, gblock>>>(c_lex, W, drive);

    // Phase 2: 50-step recurrence + selection, one warp per row
    const int write_aux = (out_size >= B * NL + 2 * B) ? 1 : 0;
    int warps_per_blk = 8;                        // 256 threads
    int nblk = (B + warps_per_blk - 1) / warps_per_blk;
    iterate_kernel<<<nblk, warps_per_blk * 32>>>(drive, a0, out, B, write_aux);
}

// round 6
// speedup vs baseline: 1.5535x; 1.5535x over previous
#include <cuda_runtime.h>
#include <cuda_bf16.h>
#include <cstdint>

// Problem constants (fixed by the reference)
#define NC   1024      // n_concepts (K)
#define NL   512       // n_lemmas   (N)
#define BTOT 4096      // batch      (M)
#define TSTEPS 50
#define GAMMA_C 0.95f
#define KAPPA_C 0.1f
#define FLOOR_C 1e-6f

// ---------------- device scratch (no runtime alloc allowed) ----------------
__device__ __align__(1024) float         g_drive[(size_t)BTOT * NL];   // 8 MB
__device__ __align__(1024) __nv_bfloat16 g_Abf[2][BTOT][NC];           // 16 MB (hi, lo)
__device__ __align__(1024) __nv_bfloat16 g_Wbf[2][NL][NC];             // 2 MB  (hi, lo)

// ---------------------------- PTX helpers (base ISA only) -------------------
__device__ __forceinline__ uint32_t smem_u32(const void* p) {
    uint32_t a;
    asm("{ .reg .u64 t; cvta.to.shared.u64 t, %1; cvt.u32.u64 %0, t; }" : "=r"(a) : "l"(p));
    return a;
}
__device__ __forceinline__ void cp16(uint32_t dst, const void* src) {
    asm volatile("cp.async.cg.shared.global [%0], [%1], 16;" :: "r"(dst), "l"(src));
}
#define CP_COMMIT() asm volatile("cp.async.commit_group;" ::: "memory")
#define CP_WAIT2()  asm volatile("cp.async.wait_group 2;" ::: "memory")

#define LDSM4(r, addr) \
    asm volatile("ldmatrix.sync.aligned.m8n8.x4.shared.b16 {%0,%1,%2,%3}, [%4];" \
        : "=r"((r)[0]), "=r"((r)[1]), "=r"((r)[2]), "=r"((r)[3]) : "r"(addr))

#define MMA16816(d, a, b0, b1) \
    asm volatile("mma.sync.aligned.m16n8k16.row.col.f32.bf16.bf16.f32 " \
        "{%0,%1,%2,%3}, {%4,%5,%6,%7}, {%8,%9}, {%0,%1,%2,%3};" \
        : "+f"((d)[0]), "+f"((d)[1]), "+f"((d)[2]), "+f"((d)[3]) \
        : "r"((a)[0]), "r"((a)[1]), "r"((a)[2]), "r"((a)[3]), "r"(b0), "r"(b1))

// ------------------------ fp32 -> bf16 hi/lo split --------------------------
__global__ __launch_bounds__(256) void convert_kernel(
    const float* __restrict__ A, const float* __restrict__ W, int nA, int nW)
{
    int i = (blockIdx.x * blockDim.x + threadIdx.x) * 4;
    const float* src;
    __nv_bfloat16 *dhi, *dlo;
    if (i < nA) {
        src = A + i;
        dhi = &g_Abf[0][0][0] + i;
        dlo = &g_Abf[1][0][0] + i;
    } else {
        int j = i - nA;
        if (j >= nW) return;
        src = W + j;
        dhi = &g_Wbf[0][0][0] + j;
        dlo = &g_Wbf[1][0][0] + j;
    }
    float4 v = *reinterpret_cast<const float4*>(src);
    __nv_bfloat16 h0 = __float2bfloat16(v.x), h1 = __float2bfloat16(v.y);
    __nv_bfloat16 h2 = __float2bfloat16(v.z), h3 = __float2bfloat16(v.w);
    __nv_bfloat16 l0 = __float2bfloat16(v.x - __bfloat162float(h0));
    __nv_bfloat16 l1 = __float2bfloat16(v.y - __bfloat162float(h1));
    __nv_bfloat16 l2 = __float2bfloat16(v.z - __bfloat162float(h2));
    __nv_bfloat16 l3 = __float2bfloat16(v.w - __bfloat162float(h3));
    reinterpret_cast<__nv_bfloat162*>(dhi)[0] = __nv_bfloat162(h0, h1);
    reinterpret_cast<__nv_bfloat162*>(dhi)[1] = __nv_bfloat162(h2, h3);
    reinterpret_cast<__nv_bfloat162*>(dlo)[0] = __nv_bfloat162(l0, l1);
    reinterpret_cast<__nv_bfloat162*>(dlo)[1] = __nv_bfloat162(l2, l3);
}

// ------------------------- HMMA GEMM ----------------------------------------
// drive[M,NL] = Ahi@Whi^T + Ahi@Wlo^T + Alo@Whi^T  as one K=3072 pass with
// per-segment plane-pointer swap. CTA 128x128, 8 warps (4M x 2N), warp 32x64.
// 4-stage cp.async pipeline, K-step 32 bf16 (64 B/row).
// Smem rows padded to 80 B -> conflict-free ldmatrix (80 = 16*5, 5 coprime 8).
#define PAD_E   40                    // padded row length in bf16 elems (80 B)
#define TILE_B  (128 * PAD_E * 2)     // 10240 B per tile per stage
#define STG     4
#define SMEM_B_OFF (STG * TILE_B)     // B tiles after A tiles
#define SMEM_TOT   (2 * STG * TILE_B) // 81920 B

__global__ __launch_bounds__(256, 1) void gemm_hmma_kernel(
    const __nv_bfloat16* __restrict__ Ahi, const __nv_bfloat16* __restrict__ Alo,
    const __nv_bfloat16* __restrict__ Whi, const __nv_bfloat16* __restrict__ Wlo,
    float* __restrict__ D)
{
    extern __shared__ __align__(128) char smem[];
    const uint32_t sb = smem_u32(smem);
    const int tid = threadIdx.x, lane = tid & 31, wid = tid >> 5;
    const int wm = wid & 3, wn = wid >> 2;          // 4 x 2 warp grid
    const int m0 = blockIdx.y * 128, n0 = blockIdx.x * 128;

    float acc[2][8][4];
    #pragma unroll
    for (int a = 0; a < 2; a++)
        #pragma unroll
        for (int b = 0; b < 8; b++)
            #pragma unroll
            for (int c = 0; c < 4; c++) acc[a][b][c] = 0.f;

    auto load_stage = [&](int it, int s) {
        const int seg = it >> 5;                     // 0,1,2
        const int k0  = (it & 31) << 5;              // k offset in plane
        const __nv_bfloat16* Ap = (seg == 2) ? Alo : Ahi;
        const __nv_bfloat16* Wp = (seg == 1) ? Wlo : Whi;
        const uint32_t da = sb + s * TILE_B;
        const uint32_t db = sb + SMEM_B_OFF + s * TILE_B;
        #pragma unroll
        for (int i = 0; i < 2; i++) {
            const int id = tid * 2 + i;              // 0..511
            const int r = id >> 2, c = id & 3;       // row, 16B chunk
            cp16(da + r * 80 + c * 16, Ap + (size_t)(m0 + r) * NC + k0 + c * 8);
            cp16(db + r * 80 + c * 16, Wp + (size_t)(n0 + r) * NC + k0 + c * 8);
        }
        CP_COMMIT();
    };

    load_stage(0, 0); load_stage(1, 1); load_stage(2, 2);

    const int NIT = 3 * (NC / 32);                   // 96
    for (int it = 0; it < NIT; ++it) {
        const int s = it & 3;
        CP_WAIT2();
        __syncthreads();
        if (it + 3 < NIT) load_stage(it + 3, (it + 3) & 3);
        else CP_COMMIT();                            // keep group count uniform

        const uint32_t aB = sb + s * TILE_B;
        const uint32_t bB = sb + SMEM_B_OFF + s * TILE_B;
        #pragma unroll
        for (int kk = 0; kk < 2; ++kk) {             // two k16 per 32-chunk
            const uint32_t kb = kk * 32 + ((lane >> 4) << 4);
            uint32_t ar[2][4], br[4][4];
            #pragma unroll
            for (int mi = 0; mi < 2; mi++) {
                const int row = wm * 32 + mi * 16 + (lane & 15);
                LDSM4(ar[mi], aB + row * 80 + kb);
            }
            #pragma unroll
            for (int ni = 0; ni < 4; ni++) {
                const int row = wn * 64 + ni * 16 + (lane & 15);
                LDSM4(br[ni], bB + row * 80 + kb);
            }
            #pragma unroll
            for (int mi = 0; mi < 2; mi++)
                #pragma unroll
                for (int ni = 0; ni < 4; ni++) {
                    MMA16816(acc[mi][ni * 2],     ar[mi], br[ni][0], br[ni][2]);
                    MMA16816(acc[mi][ni * 2 + 1], ar[mi], br[ni][1], br[ni][3]);
                }
        }
    }

    // ---- epilogue: write fp32 drive directly ----
    #pragma unroll
    for (int mi = 0; mi < 2; mi++) {
        const int row = m0 + wm * 32 + mi * 16 + (lane >> 2);
        #pragma unroll
        for (int nj = 0; nj < 8; nj++) {
            const int col = n0 + wn * 64 + nj * 8 + (lane & 3) * 2;
            *reinterpret_cast<float2*>(&D[(size_t)row * NL + col]) =
                make_float2(acc[mi][nj][0], acc[mi][nj][1]);
            *reinterpret_cast<float2*>(&D[(size_t)(row + 8) * NL + col]) =
                make_float2(acc[mi][nj][2], acc[mi][nj][3]);
        }
    }
}

// ---------------------------------------------------------------------------
// Recurrence + selection: one warp per batch row, a/d in registers.
// ---------------------------------------------------------------------------
__global__ __launch_bounds__(256) void iterate_kernel(
    const float* __restrict__ D, const float* __restrict__ a0,
    float* __restrict__ out, int B, int write_aux)
{
    const int warp = (blockIdx.x * blockDim.x + threadIdx.x) >> 5;
    const int lane = threadIdx.x & 31;
    if (warp >= B) return;

    const size_t rowoff = (size_t)warp * NL;
    float dv[16], a[16];
    #pragma unroll
    for (int i = 0; i < 16; i++) {
        dv[i] = D [rowoff + lane + 32 * i];
        a[i]  = a0[rowoff + lane + 32 * i];
    }

    const float c1 = 1.0f + KAPPA_C;
    #pragma unroll 1
    for (int t = 0; t < TSTEPS; t++) {
        float p = 0.f;
        #pragma unroll
        for (int i = 0; i < 16; i++) {
            a[i] = fmaf(GAMMA_C, a[i], dv[i]);
            p += a[i];
        }
        #pragma unroll
        for (int o = 16; o; o >>= 1) p += __shfl_xor_sync(0xffffffffu, p, o);
        const float nks = -KAPPA_C * p;
        #pragma unroll
        for (int i = 0; i < 16; i++)
            a[i] = fmaxf(fmaf(c1, a[i], nks), 0.f);
    }

    float s = 0.f, m = -1.f;
    int mi = NL;
    #pragma unroll
    for (int i = 0; i < 16; i++) {
        float v = a[i];
        s += v;
        if (v > m) { m = v; mi = lane + 32 * i; }
    }
    #pragma unroll
    for (int o = 16; o; o >>= 1) {
        float om  = __shfl_xor_sync(0xffffffffu, m,  o);
        int   omi = __shfl_xor_sync(0xffffffffu, mi, o);
        float os  = __shfl_xor_sync(0xffffffffu, s,  o);
        s += os;
        if (om > m || (om == m && omi < mi)) { m = om; mi = omi; }
    }

    #pragma unroll
    for (int i = 0; i < 16; i++)
        out[rowoff + lane + 32 * i] = a[i];

    if (lane == 0 && write_aux) {
        const size_t base = (size_t)B * NL;
        out[base + warp]     = (float)mi;
        out[base + B + warp] = m / fmaxf(s * (1.0f / NL), FLOOR_C);
    }
}

// ---------------------------------------------------------------------------
extern "C" void kernel_launch(void* const* d_in, const int* in_sizes, int n_in,
                              void* d_out, int out_size)
{
    const float* c_lex = (const float*)d_in[0];   // (B, 1024)
    const float* W     = (const float*)d_in[1];   // (512, 1024)
    const float* a0    = (const float*)d_in[2];   // (B, 512)
    float* out = (float*)d_out;

    const int B = in_sizes[0] / NC;               // 4096

    float* drive = nullptr;
    void*  abf   = nullptr;
    void*  wbf   = nullptr;
    cudaGetSymbolAddress((void**)&drive, g_drive);
    cudaGetSymbolAddress(&abf, g_Abf);
    cudaGetSymbolAddress(&wbf, g_Wbf);
    const __nv_bfloat16* Ahi = (const __nv_bfloat16*)abf;
    const __nv_bfloat16* Alo = Ahi + (size_t)BTOT * NC;
    const __nv_bfloat16* Whi = (const __nv_bfloat16*)wbf;
    const __nv_bfloat16* Wlo = Whi + (size_t)NL * NC;

    // ---- phase 0: split fp32 into bf16 hi/lo planes ----
    const int nA = B * NC, nW = NL * NC;
    const int nthr4 = (nA + nW) / 4;
    convert_kernel<<<(nthr4 + 255) / 256, 256>>>(c_lex, W, nA, nW);

    // ---- phase 1: drive via HMMA (3-term bf16 split, K=3072 fused) ----
    cudaFuncSetAttribute(gemm_hmma_kernel,
                         cudaFuncAttributeMaxDynamicSharedMemorySize, SMEM_TOT);
    dim3 ggrid(NL / 128, B / 128);   // (4, 32) = 128 CTAs, one wave
    gemm_hmma_kernel<<<ggrid, 256, SMEM_TOT>>>(Ahi, Alo, Whi, Wlo, drive);

    // ---- phase 2: 50-step recurrence + selection ----
    const int write_aux = (out_size >= B * NL + 2 * B) ? 1 : 0;
    const int warps_per_blk = 8;     // 256 threads
    const int nblk = (B + warps_per_blk - 1) / warps_per_blk;
    iterate_kernel<<<nblk, warps_per_blk * 32>>>(drive, a0, out, B, write_aux);
}

// round 7
// speedup vs baseline: 1.9016x; 1.2241x over previous
#include <cuda_runtime.h>
#include <cuda_bf16.h>
#include <cstdint>

// Problem constants (fixed by the reference)
#define NC   1024      // n_concepts (K)
#define NL   512       // n_lemmas   (N)
#define BTOT 4096      // batch      (M)
#define TSTEPS 50
#define GAMMA_C 0.95f
#define KAPPA_C 0.1f
#define FLOOR_C 1e-6f

// ---------------- device scratch (no runtime alloc allowed) ----------------
__device__ __align__(1024) float         g_drive[(size_t)BTOT * NL];   // 8 MB
__device__ __align__(1024) __nv_bfloat16 g_Abf[2][BTOT][NC];           // 16 MB (hi, lo)
__device__ __align__(1024) __nv_bfloat16 g_Wbf[2][NL][NC];             // 2 MB  (hi, lo)

// ---------------------------- PTX helpers (base ISA only) -------------------
__device__ __forceinline__ uint32_t smem_u32(const void* p) {
    uint32_t a;
    asm("{ .reg .u64 t; cvta.to.shared.u64 t, %1; cvt.u32.u64 %0, t; }" : "=r"(a) : "l"(p));
    return a;
}
__device__ __forceinline__ void cp16(uint32_t dst, const void* src) {
    asm volatile("cp.async.cg.shared.global [%0], [%1], 16;" :: "r"(dst), "l"(src));
}
#define CP_COMMIT() asm volatile("cp.async.commit_group;" ::: "memory")
#define CP_WAIT2()  asm volatile("cp.async.wait_group 2;" ::: "memory")

#define LDSM4(r, addr) \
    asm volatile("ldmatrix.sync.aligned.m8n8.x4.shared.b16 {%0,%1,%2,%3}, [%4];" \
        : "=r"((r)[0]), "=r"((r)[1]), "=r"((r)[2]), "=r"((r)[3]) : "r"(addr))

#define MMA16816(d, a, b0, b1) \
    asm volatile("mma.sync.aligned.m16n8k16.row.col.f32.bf16.bf16.f32 " \
        "{%0,%1,%2,%3}, {%4,%5,%6,%7}, {%8,%9}, {%0,%1,%2,%3};" \
        : "+f"((d)[0]), "+f"((d)[1]), "+f"((d)[2]), "+f"((d)[3]) \
        : "r"((a)[0]), "r"((a)[1]), "r"((a)[2]), "r"((a)[3]), "r"(b0), "r"(b1))

// ------------------------ fp32 -> bf16 hi/lo split --------------------------
__global__ __launch_bounds__(256) void convert_kernel(
    const float* __restrict__ A, const float* __restrict__ W, int nA, int nW)
{
    int i = (blockIdx.x * blockDim.x + threadIdx.x) * 4;
    const float* src;
    __nv_bfloat16 *dhi, *dlo;
    if (i < nA) {
        src = A + i;
        dhi = &g_Abf[0][0][0] + i;
        dlo = &g_Abf[1][0][0] + i;
    } else {
        int j = i - nA;
        if (j >= nW) return;
        src = W + j;
        dhi = &g_Wbf[0][0][0] + j;
        dlo = &g_Wbf[1][0][0] + j;
    }
    float4 v = *reinterpret_cast<const float4*>(src);
    __nv_bfloat16 h0 = __float2bfloat16(v.x), h1 = __float2bfloat16(v.y);
    __nv_bfloat16 h2 = __float2bfloat16(v.z), h3 = __float2bfloat16(v.w);
    __nv_bfloat16 l0 = __float2bfloat16(v.x - __bfloat162float(h0));
    __nv_bfloat16 l1 = __float2bfloat16(v.y - __bfloat162float(h1));
    __nv_bfloat16 l2 = __float2bfloat16(v.z - __bfloat162float(h2));
    __nv_bfloat16 l3 = __float2bfloat16(v.w - __bfloat162float(h3));
    reinterpret_cast<__nv_bfloat162*>(dhi)[0] = __nv_bfloat162(h0, h1);
    reinterpret_cast<__nv_bfloat162*>(dhi)[1] = __nv_bfloat162(h2, h3);
    reinterpret_cast<__nv_bfloat162*>(dlo)[0] = __nv_bfloat162(l0, l1);
    reinterpret_cast<__nv_bfloat162*>(dlo)[1] = __nv_bfloat162(l2, l3);
}

// ------------------------- HMMA GEMM ----------------------------------------
// drive[M,NL] = Ahi@Whi^T + Ahi@Wlo^T + Alo@Whi^T  as one K=3072 pass with
// per-segment plane-pointer swap. CTA 128x128, 8 warps (4M x 2N), warp 32x64.
// 4-stage cp.async pipeline, K-step 64 bf16 (128 B/row), rows padded to 144 B
// (16*9, 9 coprime 8 -> conflict-free ldmatrix). Fragment double-buffering
// overlaps LDSM latency with MMA issue.
#define ROW_B   144                   // padded row bytes
#define TILE_B  (128 * ROW_B)         // 18432 B per tile per stage
#define STG     4
#define SMEM_B_OFF (STG * TILE_B)     // B tiles after A tiles
#define SMEM_TOT   (2 * STG * TILE_B) // 147456 B

__global__ __launch_bounds__(256, 1) void gemm_hmma_kernel(
    const __nv_bfloat16* __restrict__ Ahi, const __nv_bfloat16* __restrict__ Alo,
    const __nv_bfloat16* __restrict__ Whi, const __nv_bfloat16* __restrict__ Wlo,
    float* __restrict__ D)
{
    extern __shared__ __align__(128) char smem[];
    const uint32_t sb = smem_u32(smem);
    const int tid = threadIdx.x, lane = tid & 31, wid = tid >> 5;
    const int wm = wid & 3, wn = wid >> 2;          // 4 x 2 warp grid
    const int m0 = blockIdx.y * 128, n0 = blockIdx.x * 128;

    float acc[2][8][4];
    #pragma unroll
    for (int a = 0; a < 2; a++)
        #pragma unroll
        for (int b = 0; b < 8; b++)
            #pragma unroll
            for (int c = 0; c < 4; c++) acc[a][b][c] = 0.f;

    // One stage = 64 K-columns of both tiles. 1024 16B-chunks per tile,
    // 4 per thread per tile, consecutive tid -> consecutive 16B (coalesced).
    auto load_stage = [&](int it, int s) {
        const int seg = it >> 4;                     // 0,1,2 (16 K64 per plane)
        const int k0  = (it & 15) << 6;
        const __nv_bfloat16* Ap = (seg == 2) ? Alo : Ahi;
        const __nv_bfloat16* Wp = (seg == 1) ? Wlo : Whi;
        const uint32_t da = sb + s * TILE_B;
        const uint32_t db = sb + SMEM_B_OFF + s * TILE_B;
        #pragma unroll
        for (int i = 0; i < 4; i++) {
            const int ci = i * 256 + tid;
            const int r = ci >> 3, c = ci & 7;
            cp16(da + r * ROW_B + c * 16, Ap + (size_t)(m0 + r) * NC + k0 + c * 8);
            cp16(db + r * ROW_B + c * 16, Wp + (size_t)(n0 + r) * NC + k0 + c * 8);
        }
        CP_COMMIT();
    };

    auto ldfrags = [&](uint32_t aB, uint32_t bB, int kk,
                       uint32_t ar[2][4], uint32_t br[4][4]) {
        const uint32_t kb = kk * 32 + ((lane >> 4) << 4);
        #pragma unroll
        for (int mi = 0; mi < 2; mi++) {
            const int row = wm * 32 + mi * 16 + (lane & 15);
            LDSM4(ar[mi], aB + row * ROW_B + kb);
        }
        #pragma unroll
        for (int ni = 0; ni < 4; ni++) {
            const int row = wn * 64 + ni * 16 + (lane & 15);
            LDSM4(br[ni], bB + row * ROW_B + kb);
        }
    };

    load_stage(0, 0); load_stage(1, 1); load_stage(2, 2);

    const int NIT = 3 * (NC / 64);                   // 48
    for (int it = 0; it < NIT; ++it) {
        const int s = it & 3;
        CP_WAIT2();
        __syncthreads();
        if (it + 3 < NIT) load_stage(it + 3, (it + 3) & 3);
        else CP_COMMIT();                            // keep group count uniform

        const uint32_t aB = sb + s * TILE_B;
        const uint32_t bB = sb + SMEM_B_OFF + s * TILE_B;

        uint32_t ar[2][2][4], br[2][4][4];
        ldfrags(aB, bB, 0, ar[0], br[0]);
        #pragma unroll
        for (int kk = 0; kk < 4; ++kk) {             // four k16 per K64 stage
            const int cur = kk & 1;
            if (kk < 3) ldfrags(aB, bB, kk + 1, ar[cur ^ 1], br[cur ^ 1]);
            #pragma unroll
            for (int mi = 0; mi < 2; mi++)
                #pragma unroll
                for (int ni = 0; ni < 4; ni++) {
                    MMA16816(acc[mi][ni * 2],     ar[cur][mi], br[cur][ni][0], br[cur][ni][2]);
                    MMA16816(acc[mi][ni * 2 + 1], ar[cur][mi], br[cur][ni][1], br[cur][ni][3]);
                }
        }
    }

    // ---- epilogue: write fp32 drive directly ----
    #pragma unroll
    for (int mi = 0; mi < 2; mi++) {
        const int row = m0 + wm * 32 + mi * 16 + (lane >> 2);
        #pragma unroll
        for (int nj = 0; nj < 8; nj++) {
            const int col = n0 + wn * 64 + nj * 8 + (lane & 3) * 2;
            *reinterpret_cast<float2*>(&D[(size_t)row * NL + col]) =
                make_float2(acc[mi][nj][0], acc[mi][nj][1]);
            *reinterpret_cast<float2*>(&D[(size_t)(row + 8) * NL + col]) =
                make_float2(acc[mi][nj][2], acc[mi][nj][3]);
        }
    }
}

// ---------------------------------------------------------------------------
// Recurrence + selection: one warp per batch row, a/d in registers.
// ---------------------------------------------------------------------------
__global__ __launch_bounds__(256) void iterate_kernel(
    const float* __restrict__ D, const float* __restrict__ a0,
    float* __restrict__ out, int B, int write_aux)
{
    const int warp = (blockIdx.x * blockDim.x + threadIdx.x) >> 5;
    const int lane = threadIdx.x & 31;
    if (warp >= B) return;

    const size_t rowoff = (size_t)warp * NL;
    float dv[16], a[16];
    #pragma unroll
    for (int i = 0; i < 16; i++) {
        dv[i] = D [rowoff + lane + 32 * i];
        a[i]  = a0[rowoff + lane + 32 * i];
    }

    const float c1 = 1.0f + KAPPA_C;
    #pragma unroll 1
    for (int t = 0; t < TSTEPS; t++) {
        float p = 0.f;
        #pragma unroll
        for (int i = 0; i < 16; i++) {
            a[i] = fmaf(GAMMA_C, a[i], dv[i]);
            p += a[i];
        }
        #pragma unroll
        for (int o = 16; o; o >>= 1) p += __shfl_xor_sync(0xffffffffu, p, o);
        const float nks = -KAPPA_C * p;
        #pragma unroll
        for (int i = 0; i < 16; i++)
            a[i] = fmaxf(fmaf(c1, a[i], nks), 0.f);
    }

    float s = 0.f, m = -1.f;
    int mi = NL;
    #pragma unroll
    for (int i = 0; i < 16; i++) {
        float v = a[i];
        s += v;
        if (v > m) { m = v; mi = lane + 32 * i; }
    }
    #pragma unroll
    for (int o = 16; o; o >>= 1) {
        float om  = __shfl_xor_sync(0xffffffffu, m,  o);
        int   omi = __shfl_xor_sync(0xffffffffu, mi, o);
        float os  = __shfl_xor_sync(0xffffffffu, s,  o);
        s += os;
        if (om > m || (om == m && omi < mi)) { m = om; mi = omi; }
    }

    #pragma unroll
    for (int i = 0; i < 16; i++)
        out[rowoff + lane + 32 * i] = a[i];

    if (lane == 0 && write_aux) {
        const size_t base = (size_t)B * NL;
        out[base + warp]     = (float)mi;
        out[base + B + warp] = m / fmaxf(s * (1.0f / NL), FLOOR_C);
    }
}

// ---------------------------------------------------------------------------
extern "C" void kernel_launch(void* const* d_in, const int* in_sizes, int n_in,
                              void* d_out, int out_size)
{
    const float* c_lex = (const float*)d_in[0];   // (B, 1024)
    const float* W     = (const float*)d_in[1];   // (512, 1024)
    const float* a0    = (const float*)d_in[2];   // (B, 512)
    float* out = (float*)d_out;

    const int B = in_sizes[0] / NC;               // 4096

    float* drive = nullptr;
    void*  abf   = nullptr;
    void*  wbf   = nullptr;
    cudaGetSymbolAddress((void**)&drive, g_drive);
    cudaGetSymbolAddress(&abf, g_Abf);
    cudaGetSymbolAddress(&wbf, g_Wbf);
    const __nv_bfloat16* Ahi = (const __nv_bfloat16*)abf;
    const __nv_bfloat16* Alo = Ahi + (size_t)BTOT * NC;
    const __nv_bfloat16* Whi = (const __nv_bfloat16*)wbf;
    const __nv_bfloat16* Wlo = Whi + (size_t)NL * NC;

    // ---- phase 0: split fp32 into bf16 hi/lo planes ----
    const int nA = B * NC, nW = NL * NC;
    const int nthr4 = (nA + nW) / 4;
    convert_kernel<<<(nthr4 + 255) / 256, 256>>>(c_lex, W, nA, nW);

    // ---- phase 1: drive via HMMA (3-term bf16 split, K=3072 fused) ----
    cudaFuncSetAttribute(gemm_hmma_kernel,
                         cudaFuncAttributeMaxDynamicSharedMemorySize, SMEM_TOT);
    dim3 ggrid(NL / 128, B / 128);   // (4, 32) = 128 CTAs, one wave
    gemm_hmma_kernel<<<ggrid, 256, SMEM_TOT>>>(Ahi, Alo, Whi, Wlo, drive);

    // ---- phase 2: 50-step recurrence + selection ----
    const int write_aux = (out_size >= B * NL + 2 * B) ? 1 : 0;
    const int warps_per_blk = 8;     // 256 threads
    const int nblk = (B + warps_per_blk - 1) / warps_per_blk;
    iterate_kernel<<<nblk, warps_per_blk * 32>>>(drive, a0, out, B, write_aux);
}

// round 8
// speedup vs baseline: 1.9901x; 1.0465x over previous
#include <cuda_runtime.h>
#include <cuda_bf16.h>
#include <cstdint>

// Problem constants (fixed by the reference)
#define NC   1024      // n_concepts (K)
#define NL   512       // n_lemmas   (N)
#define BTOT 4096      // batch      (M)
#define TSTEPS 50
#define GAMMA_C 0.95f
#define KAPPA_C 0.1f
#define FLOOR_C 1e-6f

// ---------------- device scratch (no runtime alloc allowed) ----------------
__device__ __align__(1024) float         g_drive[(size_t)BTOT * NL];   // 8 MB
__device__ __align__(1024) __nv_bfloat16 g_Abf[2][BTOT][NC];           // 16 MB (hi, lo)
__device__ __align__(1024) __nv_bfloat16 g_Wbf[2][NL][NC];             // 2 MB  (hi, lo)

// ---------------------------- PTX helpers (base ISA only) -------------------
__device__ __forceinline__ uint32_t smem_u32(const void* p) {
    uint32_t a;
    asm("{ .reg .u64 t; cvta.to.shared.u64 t, %1; cvt.u32.u64 %0, t; }" : "=r"(a) : "l"(p));
    return a;
}
__device__ __forceinline__ void cp16(uint32_t dst, const void* src) {
    asm volatile("cp.async.cg.shared.global [%0], [%1], 16;" :: "r"(dst), "l"(src));
}
#define CP_COMMIT() asm volatile("cp.async.commit_group;" ::: "memory")
#define CP_WAIT1()  asm volatile("cp.async.wait_group 1;" ::: "memory")

#define LDSM4(r, addr) \
    asm volatile("ldmatrix.sync.aligned.m8n8.x4.shared.b16 {%0,%1,%2,%3}, [%4];" \
        : "=r"((r)[0]), "=r"((r)[1]), "=r"((r)[2]), "=r"((r)[3]) : "r"(addr))

#define MMA16816(d, a, b0, b1) \
    asm volatile("mma.sync.aligned.m16n8k16.row.col.f32.bf16.bf16.f32 " \
        "{%0,%1,%2,%3}, {%4,%5,%6,%7}, {%8,%9}, {%0,%1,%2,%3};" \
        : "+f"((d)[0]), "+f"((d)[1]), "+f"((d)[2]), "+f"((d)[3]) \
        : "r"((a)[0]), "r"((a)[1]), "r"((a)[2]), "r"((a)[3]), "r"(b0), "r"(b1))

// ------------------------ fp32 -> bf16 hi/lo split (8 floats/thread) --------
__device__ __forceinline__ uint32_t pack_hi(float x, float y) {
    __nv_bfloat162 h(__float2bfloat16(x), __float2bfloat16(y));
    return *reinterpret_cast<uint32_t*>(&h);
}
__device__ __forceinline__ uint32_t pack_lo(float x, float y) {
    float rx = x - __bfloat162float(__float2bfloat16(x));
    float ry = y - __bfloat162float(__float2bfloat16(y));
    __nv_bfloat162 l(__float2bfloat16(rx), __float2bfloat16(ry));
    return *reinterpret_cast<uint32_t*>(&l);
}

__global__ __launch_bounds__(256) void convert_kernel(
    const float* __restrict__ A, const float* __restrict__ W, int nA, int nW)
{
    int i = (blockIdx.x * blockDim.x + threadIdx.x) * 8;
    const float* src;
    __nv_bfloat16 *dhi, *dlo;
    if (i < nA) {
        src = A + i;
        dhi = &g_Abf[0][0][0] + i;
        dlo = &g_Abf[1][0][0] + i;
    } else {
        int j = i - nA;
        if (j >= nW) return;
        src = W + j;
        dhi = &g_Wbf[0][0][0] + j;
        dlo = &g_Wbf[1][0][0] + j;
    }
    float4 v0 = reinterpret_cast<const float4*>(src)[0];
    float4 v1 = reinterpret_cast<const float4*>(src)[1];
    *reinterpret_cast<uint4*>(dhi) = make_uint4(
        pack_hi(v0.x, v0.y), pack_hi(v0.z, v0.w),
        pack_hi(v1.x, v1.y), pack_hi(v1.z, v1.w));
    *reinterpret_cast<uint4*>(dlo) = make_uint4(
        pack_lo(v0.x, v0.y), pack_lo(v0.z, v0.w),
        pack_lo(v1.x, v1.y), pack_lo(v1.z, v1.w));
}

// ------------------------- HMMA GEMM ----------------------------------------
// drive = Ahi@Whi^T + Ahi@Wlo^T + Alo@Whi^T, all three terms fused per K64
// chunk so Ahi/Whi fragments are reused across terms (33% less smem read
// traffic). CTA 128x128, 8 warps (4M x 2N), 3-stage cp.async pipeline.
// Stage holds 4 tiles (Ahi, Alo, Whi, Wlo), rows padded to 144 B (9*16B,
// coprime 8 -> conflict-free ldmatrix).
#define ROW_B   144
#define TILE_B  (128 * ROW_B)          // 18432 B
#define STAGE_B (4 * TILE_B)           // 73728 B
#define STG     3
#define SMEM_TOT (STG * STAGE_B)       // 221184 B

__global__ __launch_bounds__(256, 1) void gemm_hmma_kernel(
    const __nv_bfloat16* __restrict__ Ahi, const __nv_bfloat16* __restrict__ Alo,
    const __nv_bfloat16* __restrict__ Whi, const __nv_bfloat16* __restrict__ Wlo,
    float* __restrict__ D)
{
    extern __shared__ __align__(128) char smem[];
    const uint32_t sb = smem_u32(smem);
    const int tid = threadIdx.x, lane = tid & 31, wid = tid >> 5;
    const int wm = wid & 3, wn = wid >> 2;          // 4 x 2 warp grid
    const int m0 = blockIdx.y * 128, n0 = blockIdx.x * 128;

    float acc[2][8][4];
    #pragma unroll
    for (int a = 0; a < 2; a++)
        #pragma unroll
        for (int b = 0; b < 8; b++)
            #pragma unroll
            for (int c = 0; c < 4; c++) acc[a][b][c] = 0.f;

    // Load one K64 chunk: all 4 planes. 4096 16B-chunks / 256 thr = 16 each.
    auto load_chunk = [&](int c, int s) {
        const int k0 = c << 6;
        const uint32_t st = sb + s * STAGE_B;
        const __nv_bfloat16* srcs[4] = {
            Ahi + (size_t)m0 * NC + k0, Alo + (size_t)m0 * NC + k0,
            Whi + (size_t)n0 * NC + k0, Wlo + (size_t)n0 * NC + k0 };
        #pragma unroll
        for (int t = 0; t < 4; t++) {
            const uint32_t dst = st + t * TILE_B;
            const __nv_bfloat16* src = srcs[t];
            #pragma unroll
            for (int i = 0; i < 4; i++) {
                const int ci = i * 256 + tid;
                const int r = ci >> 3, cc = ci & 7;
                cp16(dst + r * ROW_B + cc * 16, src + (size_t)r * NC + cc * 8);
            }
        }
        CP_COMMIT();
    };

    load_chunk(0, 0);
    load_chunk(1, 1);

    const int NCHUNK = NC / 64;                      // 16
    for (int c = 0; c < NCHUNK; ++c) {
        const int s = c % 3;
        CP_WAIT1();
        __syncthreads();
        if (c + 2 < NCHUNK) load_chunk(c + 2, (c + 2) % 3);
        else CP_COMMIT();

        const uint32_t aHi = sb + s * STAGE_B;
        const uint32_t aLo = aHi + TILE_B;
        const uint32_t bHi = aHi + 2 * TILE_B;
        const uint32_t bLo = aHi + 3 * TILE_B;

        #pragma unroll
        for (int kk = 0; kk < 4; ++kk) {
            const uint32_t kb = kk * 32 + ((lane >> 4) << 4);
            uint32_t arh[2][4], arl[2][4], brh[4][4], brl[4][4];
            #pragma unroll
            for (int mi = 0; mi < 2; mi++) {
                const uint32_t ro = (wm * 32 + mi * 16 + (lane & 15)) * ROW_B + kb;
                LDSM4(arh[mi], aHi + ro);
                LDSM4(arl[mi], aLo + ro);
            }
            #pragma unroll
            for (int ni = 0; ni < 4; ni++) {
                const uint32_t ro = (wn * 64 + ni * 16 + (lane & 15)) * ROW_B + kb;
                LDSM4(brh[ni], bHi + ro);
                LDSM4(brl[ni], bLo + ro);
            }
            #pragma unroll
            for (int mi = 0; mi < 2; mi++)
                #pragma unroll
                for (int ni = 0; ni < 4; ni++) {
                    MMA16816(acc[mi][ni * 2],     arh[mi], brh[ni][0], brh[ni][2]);
                    MMA16816(acc[mi][ni * 2 + 1], arh[mi], brh[ni][1], brh[ni][3]);
                    MMA16816(acc[mi][ni * 2],     arh[mi], brl[ni][0], brl[ni][2]);
                    MMA16816(acc[mi][ni * 2 + 1], arh[mi], brl[ni][1], brl[ni][3]);
                    MMA16816(acc[mi][ni * 2],     arl[mi], brh[ni][0], brh[ni][2]);
                    MMA16816(acc[mi][ni * 2 + 1], arl[mi], brh[ni][1], brh[ni][3]);
                }
        }
    }

    // ---- epilogue: write fp32 drive directly ----
    #pragma unroll
    for (int mi = 0; mi < 2; mi++) {
        const int row = m0 + wm * 32 + mi * 16 + (lane >> 2);
        #pragma unroll
        for (int nj = 0; nj < 8; nj++) {
            const int col = n0 + wn * 64 + nj * 8 + (lane & 3) * 2;
            *reinterpret_cast<float2*>(&D[(size_t)row * NL + col]) =
                make_float2(acc[mi][nj][0], acc[mi][nj][1]);
            *reinterpret_cast<float2*>(&D[(size_t)(row + 8) * NL + col]) =
                make_float2(acc[mi][nj][2], acc[mi][nj][3]);
        }
    }
}

// ---------------------------------------------------------------------------
// Recurrence + selection: TWO rows per warp (ILP across the two shfl chains),
// tree-sum to cut the serial add chain. a/d in registers.
// ---------------------------------------------------------------------------
__device__ __forceinline__ float tree_sum16(const float* a) {
    float t[8];
    #pragma unroll
    for (int j = 0; j < 8; j++) t[j] = a[j] + a[j + 8];
    #pragma unroll
    for (int j = 0; j < 4; j++) t[j] += t[j + 4];
    t[0] += t[2]; t[1] += t[3];
    return t[0] + t[1];
}

__global__ __launch_bounds__(256) void iterate_kernel(
    const float* __restrict__ D, const float* __restrict__ a0,
    float* __restrict__ out, int B, int write_aux)
{
    const int warp0 = (((blockIdx.x * blockDim.x + threadIdx.x) >> 5) << 1);
    const int lane = threadIdx.x & 31;
    if (warp0 >= B) return;

    float dv[2][16], a[2][16];
    #pragma unroll
    for (int r = 0; r < 2; r++) {
        const size_t ro = (size_t)(warp0 + r) * NL;
        #pragma unroll
        for (int i = 0; i < 16; i++) {
            dv[r][i] = D [ro + lane + 32 * i];
            a[r][i]  = a0[ro + lane + 32 * i];
        }
    }

    const float c1 = 1.0f + KAPPA_C;
    #pragma unroll 1
    for (int t = 0; t < TSTEPS; t++) {
        #pragma unroll
        for (int r = 0; r < 2; r++)
            #pragma unroll
            for (int i = 0; i < 16; i++)
                a[r][i] = fmaf(GAMMA_C, a[r][i], dv[r][i]);
        float p0 = tree_sum16(a[0]);
        float p1 = tree_sum16(a[1]);
        #pragma unroll
        for (int o = 16; o; o >>= 1) {
            p0 += __shfl_xor_sync(0xffffffffu, p0, o);
            p1 += __shfl_xor_sync(0xffffffffu, p1, o);
        }
        const float k0 = -KAPPA_C * p0, k1 = -KAPPA_C * p1;
        #pragma unroll
        for (int i = 0; i < 16; i++) {
            a[0][i] = fmaxf(fmaf(c1, a[0][i], k0), 0.f);
            a[1][i] = fmaxf(fmaf(c1, a[1][i], k1), 0.f);
        }
    }

    #pragma unroll
    for (int r = 0; r < 2; r++) {
        float s = 0.f, m = -1.f;
        int mi = NL;
        #pragma unroll
        for (int i = 0; i < 16; i++) {
            float v = a[r][i];
            s += v;
            if (v > m) { m = v; mi = lane + 32 * i; }
        }
        #pragma unroll
        for (int o = 16; o; o >>= 1) {
            float om  = __shfl_xor_sync(0xffffffffu, m,  o);
            int   omi = __shfl_xor_sync(0xffffffffu, mi, o);
            float os  = __shfl_xor_sync(0xffffffffu, s,  o);
            s += os;
            if (om > m || (om == m && omi < mi)) { m = om; mi = omi; }
        }
        const size_t ro = (size_t)(warp0 + r) * NL;
        #pragma unroll
        for (int i = 0; i < 16; i++)
            out[ro + lane + 32 * i] = a[r][i];
        if (lane == 0 && write_aux) {
            const size_t base = (size_t)B * NL;
            out[base + warp0 + r]     = (float)mi;
            out[base + B + warp0 + r] = m / fmaxf(s * (1.0f / NL), FLOOR_C);
        }
    }
}

// ---------------------------------------------------------------------------
extern "C" void kernel_launch(void* const* d_in, const int* in_sizes, int n_in,
                              void* d_out, int out_size)
{
    const float* c_lex = (const float*)d_in[0];   // (B, 1024)
    const float* W     = (const float*)d_in[1];   // (512, 1024)
    const float* a0    = (const float*)d_in[2];   // (B, 512)
    float* out = (float*)d_out;

    const int B = in_sizes[0] / NC;               // 4096

    float* drive = nullptr;
    void*  abf   = nullptr;
    void*  wbf   = nullptr;
    cudaGetSymbolAddress((void**)&drive, g_drive);
    cudaGetSymbolAddress(&abf, g_Abf);
    cudaGetSymbolAddress(&wbf, g_Wbf);
    const __nv_bfloat16* Ahi = (const __nv_bfloat16*)abf;
    const __nv_bfloat16* Alo = Ahi + (size_t)BTOT * NC;
    const __nv_bfloat16* Whi = (const __nv_bfloat16*)wbf;
    const __nv_bfloat16* Wlo = Whi + (size_t)NL * NC;

    // ---- phase 0: split fp32 into bf16 hi/lo planes ----
    const int nA = B * NC, nW = NL * NC;
    const int nthr8 = (nA + nW) / 8;
    convert_kernel<<<(nthr8 + 255) / 256, 256>>>(c_lex, W, nA, nW);

    // ---- phase 1: drive via HMMA (3-term bf16 split, fused per chunk) ----
    cudaFuncSetAttribute(gemm_hmma_kernel,
                         cudaFuncAttributeMaxDynamicSharedMemorySize, SMEM_TOT);
    dim3 ggrid(NL / 128, B / 128);   // (4, 32) = 128 CTAs, one wave
    gemm_hmma_kernel<<<ggrid, 256, SMEM_TOT>>>(Ahi, Alo, Whi, Wlo, drive);

    // ---- phase 2: 50-step recurrence + selection (2 rows/warp) ----
    const int write_aux = (out_size >= B * NL + 2 * B) ? 1 : 0;
    const int nwarp = B / 2;                       // 2048 warps
    const int nblk = (nwarp * 32 + 255) / 256;     // 256 blocks
    iterate_kernel<<<nblk, 256>>>(drive, a0, out, B, write_aux);
}